// round 1
// baseline (speedup 1.0000x reference)
#include <cuda_runtime.h>
#include <cuda_bf16.h>

// Stacked-LSTM wavefront solver.
// Grid of cells (t, l), t in [0,64), l in [0,64); cell (t,l) needs (t-1,l) and (t,l-1).
// Anti-diagonals (t+l = d) are independent -> persistent kernel sweeps d = 0..126 with a
// software grid barrier between diagonals. Each diagonal is a batched GEMM with shared W:
//   z = [inp | h_prev] @ W + b   (per cell: 16x512 @ 512x1024)
// fused with the LSTM elementwise update.

#define NBLK 296   // 2 CTAs per SM (148 SMs) -> all co-resident, spin barrier is safe
#define NTHR 256
#define KT   32    // K-tile

// Persistent state (device globals: allocation-free scratch).
// h double-buffered by t-parity: h[t&1][l] holds h_l(t). c single-buffered (RMW by owner cell).
__device__ float g_c[64][16][256];
__device__ float g_h[2][64][16][256];
__device__ unsigned g_count = 0;
__device__ unsigned g_phase = 0;

__device__ __forceinline__ float sigf(float v) { return 1.0f / (1.0f + __expf(-v)); }

__device__ __forceinline__ void grid_barrier(unsigned target) {
  __syncthreads();
  if (threadIdx.x == 0) {
    __threadfence();
    if (atomicAdd(&g_count, 1) == (unsigned)(NBLK - 1)) {
      atomicExch(&g_count, 0);
      __threadfence();
      atomicAdd(&g_phase, 1);
    } else {
      while (*((volatile unsigned*)&g_phase) != target) { __nanosleep(40); }
    }
    __threadfence();
  }
  __syncthreads();
}

__global__ __launch_bounds__(NTHR, 2) void lstm_wave(
    const float* __restrict__ x,      // (16, 64, 256)
    const float* __restrict__ ist,    // (64, 2, 16, 256)
    const float* __restrict__ W,      // (512, 1024)
    const float* __restrict__ bias,   // (1024,)
    float* __restrict__ out)          // (16, 64, 256)
{
  __shared__ __align__(16) float As[KT][16];    // A^T tile: As[k][row]
  __shared__ __align__(16) float Bs[KT][256];   // W tile: Bs[k][g*64 + j] for h-slice
  __shared__ unsigned s_base;

  const int tid = threadIdx.x;
  if (tid == 0) s_base = *((volatile unsigned*)&g_phase);  // phase persists across graph replays
  __syncthreads();
  const unsigned base = s_base;

  // ---- init: c <- init_state[:,0], h(parity 1, read at t=0) <- init_state[:,1] ----
  const int total = 64 * 16 * 256;
  for (int e = blockIdx.x * NTHR + tid; e < total; e += NBLK * NTHR) {
    int l = e >> 12, rm = e & 4095;
    ((float*)g_c)[e]         = ist[(l * 2 + 0) * 4096 + rm];
    ((float*)g_h)[total + e] = ist[(l * 2 + 1) * 4096 + rm];
  }
  grid_barrier(base + 1);

  // ---- wavefront over anti-diagonals ----
  for (int d = 0; d < 127; ++d) {
    const int lo = (d > 63) ? d - 63 : 0;
    const int hi = (d < 63) ? d : 63;
    const int ncells = hi - lo + 1;
    const int njobs = ncells * 4;               // 4 h-slices of 64 cols per cell

    for (int job = blockIdx.x; job < njobs; job += NBLK) {
      const int ci = job % ncells, sl = job / ncells;
      const int l = lo + ci, t = d - l;
      const int m0 = sl * 64;
      const int pin = t & 1;            // parity where h_l(t) is written / h_{l-1}(t) was written
      const int prec = (t + 1) & 1;     // parity holding h_l(t-1) (== init slot for t=0)

      float acc[16];                    // [gate*4 + row_in_group]
      #pragma unroll
      for (int i = 0; i < 16; ++i) acc[i] = 0.0f;
      const int j = tid & 63;           // h-col within slice
      const int rg = tid >> 6;          // row group (4 rows each)

      for (int kt = 0; kt < 512; kt += KT) {
        // load W tile: Bs[k][g*64+jj] = W[kt+k][g*256 + m0 + jj]
        #pragma unroll
        for (int e4 = tid; e4 < KT * 64; e4 += NTHR) {
          int k = e4 >> 6, c = (e4 & 63) * 4;
          int g = c >> 6, jj = c & 63;
          *(float4*)&Bs[k][c] = *(const float4*)&W[(kt + k) * 1024 + g * 256 + m0 + jj];
        }
        // load A tile (transposed): As[k][r] = [inp | h_rec][r][kt+k]
        #pragma unroll
        for (int e = tid; e < KT * 16; e += NTHR) {
          int r = e >> 5, k = e & 31;
          int kg = kt + k;
          float v;
          if (kg < 256) {
            v = (l == 0) ? x[(r * 64 + t) * 256 + kg]
                         : __ldcg(&g_h[pin][l - 1][r][kg]);
          } else {
            v = __ldcg(&g_h[prec][l][r][kg - 256]);
          }
          As[k][r] = v;
        }
        __syncthreads();
        #pragma unroll 8
        for (int k = 0; k < KT; ++k) {
          float4 a = *(const float4*)&As[k][rg * 4];
          float wi = Bs[k][j];
          float wj = Bs[k][64 + j];
          float wf = Bs[k][128 + j];
          float wo = Bs[k][192 + j];
          acc[0]  += a.x * wi; acc[1]  += a.y * wi; acc[2]  += a.z * wi; acc[3]  += a.w * wi;
          acc[4]  += a.x * wj; acc[5]  += a.y * wj; acc[6]  += a.z * wj; acc[7]  += a.w * wj;
          acc[8]  += a.x * wf; acc[9]  += a.y * wf; acc[10] += a.z * wf; acc[11] += a.w * wf;
          acc[12] += a.x * wo; acc[13] += a.y * wo; acc[14] += a.z * wo; acc[15] += a.w * wo;
        }
        __syncthreads();
      }

      // fused LSTM cell elementwise
      const int m = m0 + j;
      const float bi = bias[m], bj = bias[256 + m], bf = bias[512 + m], bo = bias[768 + m];
      #pragma unroll
      for (int rr = 0; rr < 4; ++rr) {
        const int r = rg * 4 + rr;
        float zi = acc[rr]      + bi;
        float zj = acc[4 + rr]  + bj;
        float zf = acc[8 + rr]  + bf;
        float zo = acc[12 + rr] + bo;
        float lc = __ldcg(&g_c[l][r][m]);
        float nc = sigf(zf + 1.0f) * lc + sigf(zi) * tanhf(zj);
        float nh = sigf(zo) * tanhf(nc);
        __stcg(&g_c[l][r][m], nc);
        __stcg(&g_h[pin][l][r][m], nh);
        if (l == 63) out[(r * 64 + t) * 256 + m] = nh;
      }
    }
    grid_barrier(base + 2 + d);
  }
}

extern "C" void kernel_launch(void* const* d_in, const int* in_sizes, int n_in,
                              void* d_out, int out_size) {
  const float* x    = (const float*)d_in[0];
  const float* ist  = (const float*)d_in[1];
  const float* W    = (const float*)d_in[2];
  const float* bias = (const float*)d_in[3];
  float* out        = (float*)d_out;
  (void)in_sizes; (void)n_in; (void)out_size;
  lstm_wave<<<NBLK, NTHR>>>(x, ist, W, bias, out);
}